// round 1
// baseline (speedup 1.0000x reference)
#include <cuda_runtime.h>
#include <math.h>

#define BN 4
#define CCH 21
#define HH 96
#define WW 96
#define NN (HH*WW)          // 9216
#define NEH (HH*(WW-1))     // 9120 horizontal edges
#define NEV ((HH-1)*WW)     // 9120 vertical edges
#define NE  (NEH+NEV)       // 18240
#define NS  32768           // sort size (pow2)
#define NTREE 8             // (batch, tree) pairs: s = b*2 + t, t=0 low, t=1 high

// ---------------- scratch (device globals; no allocation) ----------------
__device__ double g_ws[NTREE*NS];
__device__ int    g_wi[NTREE*NS];
__device__ int    g_adj[NTREE*NN*4];
__device__ int    g_deg[NTREE*NN];
__device__ int    g_par[NTREE*NN];
__device__ int    g_ord[NTREE*NN];
__device__ int    g_loff[NTREE*(NN+4)];
__device__ int    g_nlev[NTREE];
__device__ float  g_w[NTREE*NN];            // per-node parent-edge weight
__device__ float  g_prob[BN*CCH*NN];
__device__ float  g_A[BN*(CCH+1)*NN];
__device__ float  g_S[BN*(CCH+1)*NN];
__device__ float  g_F1[BN*CCH*NN];          // filter1 output
__device__ float  g_F2[BN*CCH*NN];          // filter2 output
__device__ double g_acc[2];                 // loss sum, roi count

__device__ __forceinline__ void edge_nodes(int e, int &a, int &b) {
    if (e < NEH) { int r = e / (WW-1); int c = e - r*(WW-1); a = r*WW + c; b = a + 1; }
    else         { a = e - NEH; b = a + WW; }
}

// ---------------- kernels ----------------
__global__ void k_zero() {
    if (threadIdx.x == 0) { g_acc[0] = 0.0; g_acc[1] = 0.0; }
}

__global__ void k_sigmoid(const float* __restrict__ preds) {
    int i = blockIdx.x*blockDim.x + threadIdx.x;
    if (i < BN*CCH*NN) g_prob[i] = 1.0f/(1.0f + expf(-preds[i]));
}

__global__ void k_ew_low(const float* __restrict__ lf) {
    int idx = blockIdx.x*blockDim.x + threadIdx.x;
    if (idx >= BN*NS) return;
    int b = idx / NS, e = idx - b*NS, s = b*2;
    if (e >= NE) { g_ws[s*NS+e] = 1e300; g_wi[s*NS+e] = e; return; }
    int a, bb; edge_nodes(e, a, bb);
    const float* f = lf + b*3*NN;
    double acc = 0.0;
    #pragma unroll
    for (int c = 0; c < 3; c++) {
        double d = (double)f[c*NN+a] - (double)f[c*NN+bb];
        acc += d*d;
    }
    g_ws[s*NS+e] = acc; g_wi[s*NS+e] = e;
}

__global__ void k_ew_high(const float* __restrict__ hf) {
    int idx = blockIdx.x*blockDim.x + threadIdx.x;
    if (idx >= BN*NS) return;
    int b = idx / NS, e = idx - b*NS, s = b*2 + 1;
    if (e >= NE) { g_ws[s*NS+e] = 1e300; g_wi[s*NS+e] = e; return; }
    int a, bb; edge_nodes(e, a, bb);
    const float* f = hf + b*512*NN;
    double acc = 0.0;
    for (int c = 0; c < 512; c++) {
        double d = (double)f[c*NN+a] - (double)f[c*NN+bb];
        acc += d*d;
    }
    g_ws[s*NS+e] = acc; g_wi[s*NS+e] = e;
}

// In-place bitonic sort, one block per (b,t) segment in global memory.
__global__ void __launch_bounds__(1024) k_sort() {
    int s = blockIdx.x;
    double* ws = g_ws + s*NS;
    int*    wi = g_wi + s*NS;
    for (int k = 2; k <= NS; k <<= 1) {
        for (int j = k >> 1; j > 0; j >>= 1) {
            for (int i = threadIdx.x; i < NS; i += blockDim.x) {
                int ixj = i ^ j;
                if (ixj > i) {
                    double wa = ws[i], wb = ws[ixj];
                    int ia = wi[i], ib = wi[ixj];
                    bool up = ((i & k) == 0);
                    bool gt = (wa > wb) || (wa == wb && ia > ib);
                    if (gt == up) { ws[i] = wb; ws[ixj] = wa; wi[i] = ib; wi[ixj] = ia; }
                }
            }
            __syncthreads();
        }
    }
}

// Serial Kruskal per (b,t): union-find + sorted ids + degrees in shared memory.
__global__ void __launch_bounds__(1024) k_kruskal() {
    extern __shared__ int sh[];
    int* uf  = sh;              // NN
    int* deg = sh + NN;         // NN
    int* se  = sh + 2*NN;       // NE sorted edge ids
    int s = blockIdx.x;
    for (int i = threadIdx.x; i < NN; i += blockDim.x) { uf[i] = i; deg[i] = 0; }
    for (int i = threadIdx.x; i < NE; i += blockDim.x) { se[i] = g_wi[s*NS + i]; }
    __syncthreads();
    if (threadIdx.x == 0) {
        int* adj = g_adj + s*NN*4;
        int cnt = 0;
        for (int k = 0; k < NE && cnt < NN-1; k++) {
            int e = se[k];
            int a, b; edge_nodes(e, a, b);
            int ra = a; while (uf[ra] != ra) ra = uf[ra];
            int rb = b; while (uf[rb] != rb) rb = uf[rb];
            int x = a; while (uf[x] != ra) { int nx = uf[x]; uf[x] = ra; x = nx; }
            x = b;     while (uf[x] != rb) { int nx = uf[x]; uf[x] = rb; x = nx; }
            if (ra != rb) {
                uf[ra] = rb;
                adj[a*4 + deg[a]] = b; deg[a]++;
                adj[b*4 + deg[b]] = a; deg[b]++;
                cnt++;
            }
        }
    }
    __syncthreads();
    for (int i = threadIdx.x; i < NN; i += blockDim.x) g_deg[s*NN + i] = deg[i];
}

// Parallel level-synchronous BFS from node 0. Tree => each unvisited neighbor
// has exactly one frontier neighbor, so no visited races.
__global__ void k_bfs() {
    int s = blockIdx.x;
    __shared__ int cnt;
    int* ord  = g_ord  + s*NN;
    int* par  = g_par  + s*NN;
    int* loff = g_loff + s*(NN+4);
    const int* adj = g_adj + s*NN*4;
    const int* deg = g_deg + s*NN;
    if (threadIdx.x == 0) { ord[0] = 0; par[0] = 0; loff[0] = 0; loff[1] = 1; }
    __syncthreads();
    int cur = 0, curEnd = 1, lvl = 0;
    while (true) {
        __syncthreads();
        if (threadIdx.x == 0) cnt = 0;
        __syncthreads();
        for (int q = cur + threadIdx.x; q < curEnd; q += blockDim.x) {
            int u = ord[q];
            int pu = par[u];
            int dg = deg[u];
            for (int j = 0; j < dg; j++) {
                int v = adj[u*4 + j];
                if (v != pu) {
                    int pos = atomicAdd(&cnt, 1);
                    ord[curEnd + pos] = v;
                    par[v] = u;
                }
            }
        }
        __syncthreads();
        int c = cnt;
        if (c == 0) break;
        lvl++;
        if (threadIdx.x == 0) loff[lvl+1] = curEnd + c;
        cur = curEnd; curEnd += c;
    }
    if (threadIdx.x == 0) g_nlev[s] = lvl + 1;
}

__global__ void k_wlow(const float* __restrict__ lf) {
    int idx = blockIdx.x*blockDim.x + threadIdx.x;
    if (idx >= BN*NN) return;
    int b = idx / NN, i = idx - b*NN, s = b*2;
    int p = g_par[s*NN + i];
    const float* f = lf + b*3*NN;
    float acc = 0.0f;
    #pragma unroll
    for (int c = 0; c < 3; c++) { float d = f[c*NN+i] - f[c*NN+p]; acc += d*d; }
    g_w[s*NN + i] = (i == 0) ? 0.0f : expf(-acc/0.02f);
}

__global__ void k_whigh(const float* __restrict__ hf) {
    int gid = blockIdx.x*blockDim.x + threadIdx.x;
    int warp = gid >> 5, lane = gid & 31;
    if (warp >= BN*NN) return;
    int b = warp / NN, i = warp - b*NN, s = b*2 + 1;
    int p = g_par[s*NN + i];
    const float* f = hf + b*512*NN;
    float acc = 0.0f;
    for (int c = lane; c < 512; c += 32) { float d = f[c*NN+i] - f[c*NN+p]; acc += d*d; }
    #pragma unroll
    for (int o = 16; o; o >>= 1) acc += __shfl_xor_sync(0xFFFFFFFFu, acc, o);
    if (lane == 0) g_w[s*NN + i] = (i == 0) ? 0.0f : expf(-acc);  // sigma = 1.0
}

// Two-pass tree DP: one block per batch, level-synchronized with __syncthreads.
__global__ void __launch_bounds__(1024) k_filter(int t, int src) {
    int b = blockIdx.x, s = b*2 + t;
    const float* in = (src == 0) ? g_prob : g_F1;
    float* A = g_A + b*(CCH+1)*NN;
    float* S = g_S + b*(CCH+1)*NN;
    const int* ord  = g_ord  + s*NN;
    const int* par  = g_par  + s*NN;
    const int* loff = g_loff + s*(NN+4);
    const float* w  = g_w    + s*NN;
    int nl = g_nlev[s];
    // init: 21 data channels + norm channel of ones
    for (int i = threadIdx.x; i < CCH*NN; i += blockDim.x) A[i] = in[b*CCH*NN + i];
    for (int i = threadIdx.x; i < NN; i += blockDim.x)     A[CCH*NN + i] = 1.0f;
    __syncthreads();
    // up: leaves -> root
    for (int d = nl - 1; d >= 1; d--) {
        int s0 = loff[d], cnt = loff[d+1] - s0;
        for (int k = threadIdx.x; k < cnt*(CCH+1); k += blockDim.x) {
            int v = ord[s0 + k/(CCH+1)];
            int c = k % (CCH+1);
            atomicAdd(&A[c*NN + par[v]], w[v]*A[c*NN + v]);
        }
        __syncthreads();
    }
    // root
    for (int c = threadIdx.x; c <= CCH; c += blockDim.x) S[c*NN] = A[c*NN];
    __syncthreads();
    // down: root -> leaves
    for (int d = 1; d < nl; d++) {
        int s0 = loff[d], cnt = loff[d+1] - s0;
        for (int k = threadIdx.x; k < cnt*(CCH+1); k += blockDim.x) {
            int v = ord[s0 + k/(CCH+1)];
            int c = k % (CCH+1);
            float wv = w[v];
            float av = A[c*NN + v];
            S[c*NN + v] = av + wv*(S[c*NN + par[v]] - wv*av);
        }
        __syncthreads();
    }
}

__global__ void k_div(int dst) {
    int i = blockIdx.x*blockDim.x + threadIdx.x;
    if (i >= BN*CCH*NN) return;
    int b = i / (CCH*NN);
    int r = i - b*(CCH*NN);
    int node = r % NN;
    float* o = (dst == 0) ? g_F1 : g_F2;
    o[i] = g_S[b*(CCH+1)*NN + r] / g_S[b*(CCH+1)*NN + CCH*NN + node];
}

__global__ void k_loss(const float* __restrict__ roi) {
    __shared__ double sl[256], sn[256];
    int idx = blockIdx.x*blockDim.x + threadIdx.x;
    double l = 0.0, n = 0.0;
    if (idx < BN*NN) {
        int b = idx / NN, i = idx - b*NN;
        int h = i / WW, w = i - h*WW;
        float r = roi[b*(2*HH)*(2*WW) + (2*h)*(2*WW) + 2*w];
        n = (double)r;
        if (r != 0.0f) {
            double acc = 0.0;
            for (int c = 0; c < CCH; c++) {
                int o = b*CCH*NN + c*NN + i;
                acc += (double)fabsf(g_prob[o] - g_F2[o]);
            }
            l = acc * (double)r;
        }
    }
    sl[threadIdx.x] = l; sn[threadIdx.x] = n;
    __syncthreads();
    for (int o = 128; o; o >>= 1) {
        if (threadIdx.x < o) { sl[threadIdx.x] += sl[threadIdx.x+o]; sn[threadIdx.x] += sn[threadIdx.x+o]; }
        __syncthreads();
    }
    if (threadIdx.x == 0) { atomicAdd(&g_acc[0], sl[0]); atomicAdd(&g_acc[1], sn[0]); }
}

__global__ void k_fin(float* out) {
    if (threadIdx.x == 0)
        out[0] = (g_acc[1] > 0.0) ? (float)(g_acc[0]/g_acc[1]) : 0.0f;
}

// ---------------- launch ----------------
extern "C" void kernel_launch(void* const* d_in, const int* in_sizes, int n_in,
                              void* d_out, int out_size) {
    const float* preds = (const float*)d_in[0];
    const float* lf    = (const float*)d_in[1];
    const float* hf    = (const float*)d_in[2];
    const float* roi   = (const float*)d_in[3];
    float* out = (float*)d_out;

    static const int kruskal_smem = (2*NN + NE) * 4;  // 146688 bytes
    cudaFuncSetAttribute(k_kruskal, cudaFuncAttributeMaxDynamicSharedMemorySize, kruskal_smem);

    k_zero   <<<1, 32>>>();
    k_sigmoid<<<(BN*CCH*NN + 255)/256, 256>>>(preds);
    k_ew_low <<<(BN*NS + 255)/256, 256>>>(lf);
    k_ew_high<<<(BN*NS + 255)/256, 256>>>(hf);
    k_sort   <<<NTREE, 1024>>>();
    k_kruskal<<<NTREE, 1024, kruskal_smem>>>();
    k_bfs    <<<NTREE, 256>>>();
    k_wlow   <<<(BN*NN + 255)/256, 256>>>(lf);
    k_whigh  <<<(BN*NN*32 + 255)/256, 256>>>(hf);
    k_filter <<<BN, 1024>>>(0, 0);
    k_div    <<<(BN*CCH*NN + 255)/256, 256>>>(0);
    k_filter <<<BN, 1024>>>(1, 1);
    k_div    <<<(BN*CCH*NN + 255)/256, 256>>>(1);
    k_loss   <<<(BN*NN + 255)/256, 256>>>(roi);
    k_fin    <<<1, 32>>>(out);
}

// round 2
// speedup vs baseline: 5.0250x; 5.0250x over previous
#include <cuda_runtime.h>
#include <math.h>

#define BN 4
#define CCH 21
#define HH 96
#define WW 96
#define NN (HH*WW)          // 9216
#define NEH (HH*(WW-1))     // 9120 horizontal edges
#define NEV ((HH-1)*WW)     // 9120 vertical edges
#define NE  (NEH+NEV)       // 18240
#define NTREE 8             // (batch, tree): s = b*2 + t, t=0 low, t=1 high
#define NCHUNK 8            // channel chunks for high-feat edge weights
#define CHSZ  64            // 512 / NCHUNK

// ---------------- scratch (device globals; no allocation) ----------------
__device__ double g_ws[NTREE*NE];           // edge weights (f64, distinct => unique MST)
__device__ int    g_adj[NTREE*NN*4];        // MST adjacency (-1 = empty slot)
__device__ int    g_deg[NTREE*NN];
__device__ int    g_par[NTREE*NN];
__device__ int    g_ord[NTREE*NN];          // BFS order
__device__ int    g_loff[NTREE*(NN+4)];     // level offsets
__device__ int    g_nlev[NTREE];
__device__ float  g_w[NTREE*NN];            // per-node parent-edge weight
__device__ float  g_prob[BN*CCH*NN];
__device__ float  g_S[BN*(CCH+1)*NN];
__device__ float  g_F1[BN*CCH*NN];
__device__ float  g_F2[BN*CCH*NN];
__device__ double g_acc[2];

__device__ __forceinline__ void edge_nodes(int e, int &a, int &b) {
    if (e < NEH) { int r = e / (WW-1); int c = e - r*(WW-1); a = r*WW + c; b = a + 1; }
    else         { a = e - NEH; b = a + WW; }
}

// ---------------- kernels ----------------
__global__ void k_zero() {
    int i = blockIdx.x*blockDim.x + threadIdx.x;
    if (i < 2 && threadIdx.x < 2 && blockIdx.x == 0) g_acc[i] = 0.0;
    // zero high-tree edge-weight accumulators
    int idx = blockIdx.x*blockDim.x + threadIdx.x;
    if (idx < BN*NE) {
        int b = idx / NE, e = idx - b*NE;
        g_ws[(b*2+1)*NE + e] = 0.0;
    }
}

__global__ void k_sigmoid(const float* __restrict__ preds) {
    int i = blockIdx.x*blockDim.x + threadIdx.x;
    if (i < BN*CCH*NN) g_prob[i] = 1.0f/(1.0f + expf(-preds[i]));
}

__global__ void k_ew_low(const float* __restrict__ lf) {
    int idx = blockIdx.x*blockDim.x + threadIdx.x;
    if (idx >= BN*NE) return;
    int b = idx / NE, e = idx - b*NE;
    int a, bb; edge_nodes(e, a, bb);
    const float* f = lf + b*3*NN;
    double acc = 0.0;
    #pragma unroll
    for (int c = 0; c < 3; c++) {
        double d = (double)f[c*NN+a] - (double)f[c*NN+bb];
        acc += d*d;
    }
    g_ws[(b*2)*NE + e] = acc;
}

// chunked over channels for parallelism; merge with atomicAdd(double)
__global__ void k_ew_high(const float* __restrict__ hf) {
    int idx = blockIdx.x*blockDim.x + threadIdx.x;
    if (idx >= BN*NCHUNK*NE) return;
    int b = idx / (NCHUNK*NE);
    int r = idx - b*(NCHUNK*NE);
    int ch = r / NE, e = r - ch*NE;
    int a, bb; edge_nodes(e, a, bb);
    const float* f = hf + b*512*NN + ch*CHSZ*NN;
    double acc = 0.0;
    #pragma unroll 8
    for (int c = 0; c < CHSZ; c++) {
        double d = (double)f[c*NN+a] - (double)f[c*NN+bb];
        acc += d*d;
    }
    atomicAdd(&g_ws[(b*2+1)*NE + e], acc);
}

// Parallel Boruvka, one block per tree. Star-maintained union-find in smem.
// Distinct weights => unique MST identical to Kruskal's.
__global__ void __launch_bounds__(1024) k_boruvka() {
    extern __shared__ unsigned long long sh_u[];
    unsigned long long* minw = sh_u;                 // NN (also reused as hook target)
    int* parent = (int*)(minw + NN);                 // NN
    int* mine   = parent + NN;                       // NN
    __shared__ int total, flag;
    int s = blockIdx.x;
    const double* ws = g_ws + s*NE;
    int* adj = g_adj + s*NN*4;
    int* deg = g_deg + s*NN;
    for (int i = threadIdx.x; i < NN; i += blockDim.x) { parent[i] = i; deg[i] = 0; }
    for (int i = threadIdx.x; i < NN*4; i += blockDim.x) adj[i] = -1;
    if (threadIdx.x == 0) total = 0;
    __syncthreads();
    for (int round = 0; round < 24; round++) {
        for (int i = threadIdx.x; i < NN; i += blockDim.x) {
            minw[i] = 0xFFFFFFFFFFFFFFFFull; mine[i] = 0x7FFFFFFF;
        }
        __syncthreads();
        // pass 1: min key per component (double bits are order-preserving for >=0)
        for (int e = threadIdx.x; e < NE; e += blockDim.x) {
            int a, b; edge_nodes(e, a, b);
            int ra = parent[a], rb = parent[b];
            if (ra != rb) {
                unsigned long long k = (unsigned long long)__double_as_longlong(ws[e]);
                atomicMin(&minw[ra], k);
                atomicMin(&minw[rb], k);
            }
        }
        __syncthreads();
        // pass 2: argmin edge id (deterministic tie-break)
        for (int e = threadIdx.x; e < NE; e += blockDim.x) {
            int a, b; edge_nodes(e, a, b);
            int ra = parent[a], rb = parent[b];
            if (ra != rb) {
                unsigned long long k = (unsigned long long)__double_as_longlong(ws[e]);
                if (k == minw[ra]) atomicMin(&mine[ra], e);
                if (k == minw[rb]) atomicMin(&mine[rb], e);
            }
        }
        __syncthreads();
        // hook decision (read-only on parent), add MST edges, stash targets in minw
        for (int i = threadIdx.x; i < NN; i += blockDim.x) {
            if (parent[i] == i && mine[i] != 0x7FFFFFFF) {
                int e = mine[i];
                int a, b; edge_nodes(e, a, b);
                int ra = parent[a], rb = parent[b];
                int other = (ra == i) ? rb : ra;
                bool mutual = (mine[other] == e);
                if (!mutual || i < other) {
                    int da = atomicAdd(&deg[a], 1); adj[a*4+da] = b;
                    int db = atomicAdd(&deg[b], 1); adj[b*4+db] = a;
                    atomicAdd(&total, 1);
                    minw[i] = (unsigned long long)other;
                } else {
                    minw[i] = (unsigned long long)i;  // mutual loser stays root
                }
            } else {
                minw[i] = 0xFFFFFFFFFFFFFFFFull;
            }
        }
        __syncthreads();
        // apply hooks
        for (int i = threadIdx.x; i < NN; i += blockDim.x) {
            unsigned long long t = minw[i];
            if (t != 0xFFFFFFFFFFFFFFFFull) parent[i] = (int)t;
        }
        __syncthreads();
        // flatten to star
        for (;;) {
            if (threadIdx.x == 0) flag = 0;
            __syncthreads();
            for (int i = threadIdx.x; i < NN; i += blockDim.x) {
                int p = parent[i], gp = parent[p];
                if (p != gp) { parent[i] = gp; flag = 1; }
            }
            __syncthreads();
            int f = flag;
            __syncthreads();
            if (!f) break;
        }
        if (total >= NN-1) break;
    }
}

// Level-synchronous BFS from node 0, adjacency + frontier in shared memory.
__global__ void __launch_bounds__(512) k_bfs() {
    extern __shared__ int sh[];
    int* adj_s = sh;           // NN*4
    int* ord   = adj_s + NN*4; // NN
    int* par   = ord + NN;     // NN
    __shared__ int cnt;
    int s = blockIdx.x;
    const int* adj = g_adj + s*NN*4;
    int* loff = g_loff + s*(NN+4);
    for (int i = threadIdx.x; i < NN*4; i += blockDim.x) adj_s[i] = adj[i];
    if (threadIdx.x == 0) { ord[0] = 0; par[0] = 0; loff[0] = 0; loff[1] = 1; }
    __syncthreads();
    int cur = 0, curEnd = 1, lvl = 0;
    for (;;) {
        if (threadIdx.x == 0) cnt = 0;
        __syncthreads();
        for (int q = cur + threadIdx.x; q < curEnd; q += blockDim.x) {
            int u = ord[q], pu = par[u];
            #pragma unroll
            for (int j = 0; j < 4; j++) {
                int v = adj_s[u*4 + j];
                if (v >= 0 && v != pu) {
                    int pos = atomicAdd(&cnt, 1);
                    ord[curEnd + pos] = v;
                    par[v] = u;
                }
            }
        }
        __syncthreads();
        int c = cnt;
        __syncthreads();
        if (c == 0) break;
        lvl++;
        if (threadIdx.x == 0) loff[lvl+1] = curEnd + c;
        cur = curEnd; curEnd += c;
    }
    if (threadIdx.x == 0) g_nlev[s] = lvl + 1;
    for (int i = threadIdx.x; i < NN; i += blockDim.x) {
        g_ord[s*NN + i] = ord[i];
        g_par[s*NN + i] = par[i];
    }
}

__global__ void k_wlow(const float* __restrict__ lf) {
    int idx = blockIdx.x*blockDim.x + threadIdx.x;
    if (idx >= BN*NN) return;
    int b = idx / NN, i = idx - b*NN, s = b*2;
    int p = g_par[s*NN + i];
    const float* f = lf + b*3*NN;
    float acc = 0.0f;
    #pragma unroll
    for (int c = 0; c < 3; c++) { float d = f[c*NN+i] - f[c*NN+p]; acc += d*d; }
    g_w[s*NN + i] = (i == 0) ? 0.0f : expf(-acc/0.02f);
}

__global__ void k_whigh(const float* __restrict__ hf) {
    int gid = blockIdx.x*blockDim.x + threadIdx.x;
    int warp = gid >> 5, lane = gid & 31;
    if (warp >= BN*NN) return;
    int b = warp / NN, i = warp - b*NN, s = b*2 + 1;
    int p = g_par[s*NN + i];
    const float* f = hf + b*512*NN;
    float acc = 0.0f;
    for (int c = lane; c < 512; c += 32) { float d = f[c*NN+i] - f[c*NN+p]; acc += d*d; }
    #pragma unroll
    for (int o = 16; o; o >>= 1) acc += __shfl_xor_sync(0xFFFFFFFFu, acc, o);
    if (lane == 0) g_w[s*NN + i] = (i == 0) ? 0.0f : expf(-acc);  // sigma = 1.0
}

// Two-pass tree DP, one block per (batch, channel), all state in shared memory.
__global__ void __launch_bounds__(256) k_filter(int t, int srcsel) {
    extern __shared__ float shf[];
    float* A = shf;            // NN
    float* S = A + NN;         // NN
    float* w = S + NN;         // NN
    int* par = (int*)(w + NN); // NN
    int* ord = par + NN;       // NN
    int b = blockIdx.x, c = blockIdx.y;
    int s = b*2 + t;
    const float* in = (srcsel == 0) ? g_prob : g_F1;
    const int* loff = g_loff + s*(NN+4);
    int nl = g_nlev[s];
    for (int i = threadIdx.x; i < NN; i += blockDim.x) {
        A[i]   = (c == CCH) ? 1.0f : in[(b*CCH + c)*NN + i];
        w[i]   = g_w[s*NN + i];
        par[i] = g_par[s*NN + i];
        ord[i] = g_ord[s*NN + i];
    }
    __syncthreads();
    // up: leaves -> root
    for (int d = nl - 1; d >= 1; d--) {
        int s0 = loff[d], cnt2 = loff[d+1] - s0;
        for (int k = threadIdx.x; k < cnt2; k += blockDim.x) {
            int v = ord[s0 + k];
            atomicAdd(&A[par[v]], w[v]*A[v]);
        }
        __syncthreads();
    }
    if (threadIdx.x == 0) S[0] = A[0];  // root is node 0
    __syncthreads();
    // down: root -> leaves
    for (int d = 1; d < nl; d++) {
        int s0 = loff[d], cnt2 = loff[d+1] - s0;
        for (int k = threadIdx.x; k < cnt2; k += blockDim.x) {
            int v = ord[s0 + k];
            float wv = w[v], av = A[v];
            S[v] = av + wv*(S[par[v]] - wv*av);
        }
        __syncthreads();
    }
    float* outS = g_S + (b*(CCH+1) + c)*NN;
    for (int i = threadIdx.x; i < NN; i += blockDim.x) outS[i] = S[i];
}

__global__ void k_div(int dst) {
    int i = blockIdx.x*blockDim.x + threadIdx.x;
    if (i >= BN*CCH*NN) return;
    int b = i / (CCH*NN);
    int r = i - b*(CCH*NN);
    int node = r % NN;
    float* o = (dst == 0) ? g_F1 : g_F2;
    o[i] = g_S[b*(CCH+1)*NN + r] / g_S[b*(CCH+1)*NN + CCH*NN + node];
}

__global__ void k_loss(const float* __restrict__ roi) {
    __shared__ double sl[256], sn[256];
    int idx = blockIdx.x*blockDim.x + threadIdx.x;
    double l = 0.0, n = 0.0;
    if (idx < BN*NN) {
        int b = idx / NN, i = idx - b*NN;
        int h = i / WW, w = i - h*WW;
        float r = roi[b*(2*HH)*(2*WW) + (2*h)*(2*WW) + 2*w];
        n = (double)r;
        if (r != 0.0f) {
            double acc = 0.0;
            for (int c = 0; c < CCH; c++) {
                int o = b*CCH*NN + c*NN + i;
                acc += (double)fabsf(g_prob[o] - g_F2[o]);
            }
            l = acc * (double)r;
        }
    }
    sl[threadIdx.x] = l; sn[threadIdx.x] = n;
    __syncthreads();
    for (int o = 128; o; o >>= 1) {
        if (threadIdx.x < o) { sl[threadIdx.x] += sl[threadIdx.x+o]; sn[threadIdx.x] += sn[threadIdx.x+o]; }
        __syncthreads();
    }
    if (threadIdx.x == 0) { atomicAdd(&g_acc[0], sl[0]); atomicAdd(&g_acc[1], sn[0]); }
}

__global__ void k_fin(float* out) {
    if (threadIdx.x == 0)
        out[0] = (g_acc[1] > 0.0) ? (float)(g_acc[0]/g_acc[1]) : 0.0f;
}

// ---------------- launch ----------------
extern "C" void kernel_launch(void* const* d_in, const int* in_sizes, int n_in,
                              void* d_out, int out_size) {
    const float* preds = (const float*)d_in[0];
    const float* lf    = (const float*)d_in[1];
    const float* hf    = (const float*)d_in[2];
    const float* roi   = (const float*)d_in[3];
    float* out = (float*)d_out;

    const int smem_boruvka = NN*8 + 2*NN*4;     // 147456
    const int smem_bfs     = 6*NN*4;            // 221184
    const int smem_filter  = 5*NN*4;            // 184320
    cudaFuncSetAttribute(k_boruvka, cudaFuncAttributeMaxDynamicSharedMemorySize, smem_boruvka);
    cudaFuncSetAttribute(k_bfs,     cudaFuncAttributeMaxDynamicSharedMemorySize, smem_bfs);
    cudaFuncSetAttribute(k_filter,  cudaFuncAttributeMaxDynamicSharedMemorySize, smem_filter);

    k_zero   <<<(BN*NE + 255)/256, 256>>>();
    k_sigmoid<<<(BN*CCH*NN + 255)/256, 256>>>(preds);
    k_ew_low <<<(BN*NE + 255)/256, 256>>>(lf);
    k_ew_high<<<(BN*NCHUNK*NE + 255)/256, 256>>>(hf);
    k_boruvka<<<NTREE, 1024, smem_boruvka>>>();
    k_bfs    <<<NTREE, 512, smem_bfs>>>();
    k_wlow   <<<(BN*NN + 255)/256, 256>>>(lf);
    k_whigh  <<<(BN*NN*32 + 255)/256, 256>>>(hf);
    {
        dim3 g1(BN, CCH+1);
        k_filter<<<g1, 256, smem_filter>>>(0, 0);
        k_div   <<<(BN*CCH*NN + 255)/256, 256>>>(0);
        k_filter<<<g1, 256, smem_filter>>>(1, 1);
        k_div   <<<(BN*CCH*NN + 255)/256, 256>>>(1);
    }
    k_loss   <<<(BN*NN + 255)/256, 256>>>(roi);
    k_fin    <<<1, 32>>>(out);
}

// round 3
// speedup vs baseline: 8.9177x; 1.7747x over previous
#include <cuda_runtime.h>
#include <math.h>

#define BN 4
#define CCH 21
#define HH 96
#define WW 96
#define NN (HH*WW)          // 9216
#define NEH (HH*(WW-1))     // 9120 horizontal edges
#define NEV ((HH-1)*WW)     // 9120 vertical edges
#define NE  (NEH+NEV)       // 18240
#define NTREE 8             // (batch, tree): s = b*2 + t, t=0 low, t=1 high
#define NCHUNK 32           // channel chunks for high-feat edge weights
#define CHSZ  16            // 512 / NCHUNK

// ---------------- scratch (device globals; no allocation) ----------------
__device__ double g_ws[NTREE*NE];           // edge weights (f64, distinct => unique MST)
__device__ int    g_adj[NTREE*NN*4];        // MST adjacency (-1 = empty)
__device__ int    g_deg[NTREE*NN];
__device__ int    g_par[NTREE*NN];
__device__ int    g_ord[NTREE*NN];          // BFS order
__device__ int    g_loff[NTREE*(NN+4)];     // level offsets
__device__ int    g_nlev[NTREE];
__device__ float  g_w[NTREE*NN];            // per-node parent-edge weight
__device__ float  g_prob[BN*CCH*NN];
__device__ float  g_S[BN*(CCH+1)*NN];       // filter1 sums
__device__ float  g_S2[BN*(CCH+1)*NN];      // filter2 sums
__device__ double g_acc[2];

__device__ __forceinline__ void edge_nodes(int e, int &a, int &b) {
    if (e < NEH) { int r = e / (WW-1); int c = e - r*(WW-1); a = r*WW + c; b = a + 1; }
    else         { a = e - NEH; b = a + WW; }
}

// ---------------- kernels ----------------
__global__ void k_zero() {
    int idx = blockIdx.x*blockDim.x + threadIdx.x;
    if (idx < 2) g_acc[idx] = 0.0;
    if (idx < BN*NE) {
        int b = idx / NE, e = idx - b*NE;
        g_ws[(b*2+1)*NE + e] = 0.0;
    }
}

__global__ void k_sigmoid(const float* __restrict__ preds) {
    int i = blockIdx.x*blockDim.x + threadIdx.x;
    if (i < BN*CCH*NN) g_prob[i] = 1.0f/(1.0f + expf(-preds[i]));
}

__global__ void k_ew_low(const float* __restrict__ lf) {
    int idx = blockIdx.x*blockDim.x + threadIdx.x;
    if (idx >= BN*NE) return;
    int b = idx / NE, e = idx - b*NE;
    int a, bb; edge_nodes(e, a, bb);
    const float* f = lf + b*3*NN;
    double acc = 0.0;
    #pragma unroll
    for (int c = 0; c < 3; c++) {
        double d = (double)f[c*NN+a] - (double)f[c*NN+bb];
        acc += d*d;
    }
    g_ws[(b*2)*NE + e] = acc;
}

// chunked over channels, 4 independent accumulators to break the DFMA chain
__global__ void k_ew_high(const float* __restrict__ hf) {
    int idx = blockIdx.x*blockDim.x + threadIdx.x;
    if (idx >= BN*NCHUNK*NE) return;
    int b = idx / (NCHUNK*NE);
    int r = idx - b*(NCHUNK*NE);
    int ch = r / NE, e = r - ch*NE;
    int a, bb; edge_nodes(e, a, bb);
    const float* f = hf + b*512*NN + ch*CHSZ*NN;
    double a0 = 0.0, a1 = 0.0, a2 = 0.0, a3 = 0.0;
    #pragma unroll
    for (int c = 0; c < CHSZ; c += 4) {
        double d0 = (double)f[(c+0)*NN+a] - (double)f[(c+0)*NN+bb];
        double d1 = (double)f[(c+1)*NN+a] - (double)f[(c+1)*NN+bb];
        double d2 = (double)f[(c+2)*NN+a] - (double)f[(c+2)*NN+bb];
        double d3 = (double)f[(c+3)*NN+a] - (double)f[(c+3)*NN+bb];
        a0 += d0*d0; a1 += d1*d1; a2 += d2*d2; a3 += d3*d3;
    }
    atomicAdd(&g_ws[(b*2+1)*NE + e], (a0+a1)+(a2+a3));
}

// Parallel Boruvka, one block per tree. Star-maintained union-find in smem.
__global__ void __launch_bounds__(1024) k_boruvka() {
    extern __shared__ unsigned long long sh_u[];
    unsigned long long* minw = sh_u;                 // NN (reused as hook target)
    int* parent = (int*)(minw + NN);                 // NN
    int* mine   = parent + NN;                       // NN
    __shared__ int total, flag;
    int s = blockIdx.x;
    const double* ws = g_ws + s*NE;
    int* adj = g_adj + s*NN*4;
    int* deg = g_deg + s*NN;
    for (int i = threadIdx.x; i < NN; i += blockDim.x) { parent[i] = i; deg[i] = 0; }
    for (int i = threadIdx.x; i < NN*4; i += blockDim.x) adj[i] = -1;
    if (threadIdx.x == 0) total = 0;
    __syncthreads();
    for (int round = 0; round < 24; round++) {
        for (int i = threadIdx.x; i < NN; i += blockDim.x) {
            minw[i] = 0xFFFFFFFFFFFFFFFFull; mine[i] = 0x7FFFFFFF;
        }
        __syncthreads();
        // pass 1: min key per component (double bits order-preserving for >=0)
        for (int e = threadIdx.x; e < NE; e += blockDim.x) {
            int a, b; edge_nodes(e, a, b);
            int ra = parent[a], rb = parent[b];
            if (ra != rb) {
                unsigned long long k = (unsigned long long)__double_as_longlong(ws[e]);
                atomicMin(&minw[ra], k);
                atomicMin(&minw[rb], k);
            }
        }
        __syncthreads();
        // pass 2: argmin edge id (unique since weights distinct -> plain store)
        for (int e = threadIdx.x; e < NE; e += blockDim.x) {
            int a, b; edge_nodes(e, a, b);
            int ra = parent[a], rb = parent[b];
            if (ra != rb) {
                unsigned long long k = (unsigned long long)__double_as_longlong(ws[e]);
                if (k == minw[ra]) mine[ra] = e;
                if (k == minw[rb]) mine[rb] = e;
            }
        }
        __syncthreads();
        // hook decision, add MST edges, stash targets in minw
        for (int i = threadIdx.x; i < NN; i += blockDim.x) {
            if (parent[i] == i && mine[i] != 0x7FFFFFFF) {
                int e = mine[i];
                int a, b; edge_nodes(e, a, b);
                int ra = parent[a], rb = parent[b];
                int other = (ra == i) ? rb : ra;
                bool mutual = (mine[other] == e);
                if (!mutual || i < other) {
                    int da = atomicAdd(&deg[a], 1); adj[a*4+da] = b;
                    int db = atomicAdd(&deg[b], 1); adj[b*4+db] = a;
                    atomicAdd(&total, 1);
                    minw[i] = (unsigned long long)other;
                } else {
                    minw[i] = (unsigned long long)i;
                }
            } else {
                minw[i] = 0xFFFFFFFFFFFFFFFFull;
            }
        }
        __syncthreads();
        for (int i = threadIdx.x; i < NN; i += blockDim.x) {
            unsigned long long t = minw[i];
            if (t != 0xFFFFFFFFFFFFFFFFull) parent[i] = (int)t;
        }
        __syncthreads();
        // flatten to star
        for (;;) {
            if (threadIdx.x == 0) flag = 0;
            __syncthreads();
            for (int i = threadIdx.x; i < NN; i += blockDim.x) {
                int p = parent[i], gp = parent[p];
                if (p != gp) { parent[i] = gp; flag = 1; }
            }
            __syncthreads();
            int f = flag;
            __syncthreads();
            if (!f) break;
        }
        if (total >= NN-1) break;
    }
}

// Level-synchronous BFS from node 0, all state in shared memory.
__global__ void __launch_bounds__(512) k_bfs() {
    extern __shared__ int sh[];
    int* adj_s = sh;           // NN*4
    int* ord   = adj_s + NN*4; // NN
    int* par   = ord + NN;     // NN
    __shared__ int cnt;
    int s = blockIdx.x;
    const int* adj = g_adj + s*NN*4;
    int* loff = g_loff + s*(NN+4);
    for (int i = threadIdx.x; i < NN*4; i += blockDim.x) adj_s[i] = adj[i];
    if (threadIdx.x == 0) { ord[0] = 0; par[0] = 0; loff[0] = 0; loff[1] = 1; }
    __syncthreads();
    int cur = 0, curEnd = 1, lvl = 0;
    for (;;) {
        if (threadIdx.x == 0) cnt = 0;
        __syncthreads();
        for (int q = cur + threadIdx.x; q < curEnd; q += blockDim.x) {
            int u = ord[q], pu = par[u];
            #pragma unroll
            for (int j = 0; j < 4; j++) {
                int v = adj_s[u*4 + j];
                if (v >= 0 && v != pu) {
                    int pos = atomicAdd(&cnt, 1);
                    ord[curEnd + pos] = v;
                    par[v] = u;
                }
            }
        }
        __syncthreads();
        int c = cnt;
        __syncthreads();
        if (c == 0) break;
        lvl++;
        if (threadIdx.x == 0) loff[lvl+1] = curEnd + c;
        cur = curEnd; curEnd += c;
    }
    if (threadIdx.x == 0) g_nlev[s] = lvl + 1;
    for (int i = threadIdx.x; i < NN; i += blockDim.x) {
        g_ord[s*NN + i] = ord[i];
        g_par[s*NN + i] = par[i];
    }
}

// Parent-edge weights from precomputed edge distances (MST edges are grid edges).
__global__ void k_w() {
    int idx = blockIdx.x*blockDim.x + threadIdx.x;
    if (idx >= NTREE*NN) return;
    int s = idx / NN, i = idx - s*NN;
    if (i == 0) { g_w[idx] = 0.0f; return; }
    int p = g_par[s*NN + i];
    int e;
    if      (p == i-1)  { int r = i/WW, c = i%WW; e = r*(WW-1) + (c-1); }
    else if (p == i+1)  { int r = i/WW, c = i%WW; e = r*(WW-1) + c; }
    else if (p == i-WW) { e = NEH + (i-WW); }
    else                { e = NEH + i; }
    float sig = (s & 1) ? 1.0f : 0.02f;
    g_w[idx] = expf(-(float)g_ws[s*NE + e] / sig);
}

// Two-pass tree DP, one block per (batch, channel), state in shared memory.
// srcsel: 0 -> prob; 1 -> g_S[c]/g_S[norm] (fused division). dst: 0 -> g_S, 1 -> g_S2.
__global__ void __launch_bounds__(256) k_filter(int t, int srcsel, int dst) {
    extern __shared__ float shf[];
    float* A = shf;            // NN
    float* S = A + NN;         // NN
    float* w = S + NN;         // NN
    int* par = (int*)(w + NN); // NN
    int* ord = par + NN;       // NN
    int b = blockIdx.x, c = blockIdx.y;
    int s = b*2 + t;
    const int* loff = g_loff + s*(NN+4);
    int nl = g_nlev[s];
    const float* s1c = g_S + (b*(CCH+1) + c)*NN;
    const float* s1n = g_S + (b*(CCH+1) + CCH)*NN;
    for (int i = threadIdx.x; i < NN; i += blockDim.x) {
        float v;
        if (c == CCH)           v = 1.0f;
        else if (srcsel == 0)   v = g_prob[(b*CCH + c)*NN + i];
        else                    v = s1c[i] / s1n[i];
        A[i]   = v;
        w[i]   = g_w[s*NN + i];
        par[i] = g_par[s*NN + i];
        ord[i] = g_ord[s*NN + i];
    }
    __syncthreads();
    // up: leaves -> root
    for (int d = nl - 1; d >= 1; d--) {
        int s0 = loff[d], cnt2 = loff[d+1] - s0;
        for (int k = threadIdx.x; k < cnt2; k += blockDim.x) {
            int v = ord[s0 + k];
            atomicAdd(&A[par[v]], w[v]*A[v]);
        }
        __syncthreads();
    }
    if (threadIdx.x == 0) S[0] = A[0];
    __syncthreads();
    // down: root -> leaves
    for (int d = 1; d < nl; d++) {
        int s0 = loff[d], cnt2 = loff[d+1] - s0;
        for (int k = threadIdx.x; k < cnt2; k += blockDim.x) {
            int v = ord[s0 + k];
            float wv = w[v], av = A[v];
            S[v] = av + wv*(S[par[v]] - wv*av);
        }
        __syncthreads();
    }
    float* outS = ((dst == 0) ? g_S : g_S2) + (b*(CCH+1) + c)*NN;
    for (int i = threadIdx.x; i < NN; i += blockDim.x) outS[i] = S[i];
}

__global__ void k_loss(const float* __restrict__ roi) {
    __shared__ double sl[256], sn[256];
    int idx = blockIdx.x*blockDim.x + threadIdx.x;
    double l = 0.0, n = 0.0;
    if (idx < BN*NN) {
        int b = idx / NN, i = idx - b*NN;
        int h = i / WW, w = i - h*WW;
        float r = roi[b*(2*HH)*(2*WW) + (2*h)*(2*WW) + 2*w];
        n = (double)r;
        if (r != 0.0f) {
            float nrm = g_S2[(b*(CCH+1) + CCH)*NN + i];
            double acc = 0.0;
            for (int c = 0; c < CCH; c++) {
                float as = g_S2[(b*(CCH+1) + c)*NN + i] / nrm;
                acc += (double)fabsf(g_prob[(b*CCH + c)*NN + i] - as);
            }
            l = acc * (double)r;
        }
    }
    sl[threadIdx.x] = l; sn[threadIdx.x] = n;
    __syncthreads();
    for (int o = 128; o; o >>= 1) {
        if (threadIdx.x < o) { sl[threadIdx.x] += sl[threadIdx.x+o]; sn[threadIdx.x] += sn[threadIdx.x+o]; }
        __syncthreads();
    }
    if (threadIdx.x == 0) { atomicAdd(&g_acc[0], sl[0]); atomicAdd(&g_acc[1], sn[0]); }
}

__global__ void k_fin(float* out) {
    if (threadIdx.x == 0)
        out[0] = (g_acc[1] > 0.0) ? (float)(g_acc[0]/g_acc[1]) : 0.0f;
}

// ---------------- launch ----------------
extern "C" void kernel_launch(void* const* d_in, const int* in_sizes, int n_in,
                              void* d_out, int out_size) {
    const float* preds = (const float*)d_in[0];
    const float* lf    = (const float*)d_in[1];
    const float* hf    = (const float*)d_in[2];
    const float* roi   = (const float*)d_in[3];
    float* out = (float*)d_out;

    const int smem_boruvka = NN*8 + 2*NN*4;     // 147456
    const int smem_bfs     = 6*NN*4;            // 221184
    const int smem_filter  = 5*NN*4;            // 184320
    cudaFuncSetAttribute(k_boruvka, cudaFuncAttributeMaxDynamicSharedMemorySize, smem_boruvka);
    cudaFuncSetAttribute(k_bfs,     cudaFuncAttributeMaxDynamicSharedMemorySize, smem_bfs);
    cudaFuncSetAttribute(k_filter,  cudaFuncAttributeMaxDynamicSharedMemorySize, smem_filter);

    k_zero   <<<(BN*NE + 255)/256, 256>>>();
    k_sigmoid<<<(BN*CCH*NN + 255)/256, 256>>>(preds);
    k_ew_low <<<(BN*NE + 255)/256, 256>>>(lf);
    k_ew_high<<<(BN*NCHUNK*NE + 255)/256, 256>>>(hf);
    k_boruvka<<<NTREE, 1024, smem_boruvka>>>();
    k_bfs    <<<NTREE, 512, smem_bfs>>>();
    k_w      <<<(NTREE*NN + 255)/256, 256>>>();
    {
        dim3 g1(BN, CCH+1);
        k_filter<<<g1, 256, smem_filter>>>(0, 0, 0);
        k_filter<<<g1, 256, smem_filter>>>(1, 1, 1);
    }
    k_loss   <<<(BN*NN + 255)/256, 256>>>(roi);
    k_fin    <<<1, 32>>>(out);
}

// round 4
// speedup vs baseline: 11.2167x; 1.2578x over previous
#include <cuda_runtime.h>
#include <math.h>

#define BN 4
#define CCH 21
#define HH 96
#define WW 96
#define NN (HH*WW)          // 9216
#define NEH (HH*(WW-1))     // 9120
#define NEV ((HH-1)*WW)     // 9120
#define NE  (NEH+NEV)       // 18240
#define NTREE 8             // s = b*2 + t, t=0 low, t=1 high
#define NCHUNK 32
#define CHSZ  16            // 512 / NCHUNK

// ---------------- scratch ----------------
__device__ double g_ws[NTREE*NE];                 // edge squared distances (f64)
__device__ unsigned long long g_key[NTREE*NE];    // packed sort key: (f64bits & ~0x7FFF) | e
__device__ double g_part[BN*NCHUNK*NE];           // df64 partials for high tree
__device__ int    g_adj[NTREE*NN*4];
__device__ int    g_deg[NTREE*NN];
__device__ int    g_par[NTREE*NN];
__device__ int    g_ord[NTREE*NN];
__device__ int    g_loff[NTREE*(NN+4)];
__device__ int    g_nlev[NTREE];
__device__ float  g_w[NTREE*NN];
__device__ float  g_prob[BN*CCH*NN];
__device__ float  g_S[BN*(CCH+1)*NN];
__device__ float  g_S2[BN*(CCH+1)*NN];
__device__ double g_acc[2];

__device__ __forceinline__ void edge_nodes(int e, int &a, int &b) {
    if (e < NEH) { int r = e / (WW-1); int c = e - r*(WW-1); a = r*WW + c; b = a + 1; }
    else         { a = e - NEH; b = a + WW; }
}

__device__ __forceinline__ unsigned long long pack_key(double w, int e) {
    unsigned long long kb = (unsigned long long)__double_as_longlong(w);
    return (kb & ~32767ull) | (unsigned long long)e;
}

__device__ __forceinline__ void two_sum(float a, float b, float &s, float &e) {
    s = __fadd_rn(a, b);
    float bp = __fsub_rn(s, a);
    e = __fadd_rn(__fsub_rn(a, __fsub_rn(s, bp)), __fsub_rn(b, bp));
}

// ---------------- kernels ----------------
__global__ void k_zero() {
    int i = blockIdx.x*blockDim.x + threadIdx.x;
    if (i < 2) g_acc[i] = 0.0;
}

__global__ void k_sigmoid(const float* __restrict__ preds) {
    int i = blockIdx.x*blockDim.x + threadIdx.x;
    if (i < BN*CCH*NN) g_prob[i] = 1.0f/(1.0f + expf(-preds[i]));
}

__global__ void k_ew_low(const float* __restrict__ lf) {
    int idx = blockIdx.x*blockDim.x + threadIdx.x;
    if (idx >= BN*NE) return;
    int b = idx / NE, e = idx - b*NE;
    int a, bb; edge_nodes(e, a, bb);
    const float* f = lf + b*3*NN;
    double acc = 0.0;
    #pragma unroll
    for (int c = 0; c < 3; c++) {
        double d = (double)f[c*NN+a] - (double)f[c*NN+bb];
        acc += d*d;
    }
    int s = b*2;
    g_ws[s*NE + e] = acc;
    g_key[s*NE + e] = pack_key(acc, e);
}

// df64 (float-float) squared distance on the fp32 pipe; partials per chunk.
__global__ void k_ew_high(const float* __restrict__ hf) {
    int idx = blockIdx.x*blockDim.x + threadIdx.x;
    if (idx >= BN*NCHUNK*NE) return;
    int b = idx / (NCHUNK*NE);
    int r = idx - b*(NCHUNK*NE);
    int ch = r / NE, e = r - ch*NE;
    int a, bb; edge_nodes(e, a, bb);
    const float* f = hf + b*512*NN + ch*CHSZ*NN;
    float sh = 0.0f, sl = 0.0f;
    #pragma unroll
    for (int c = 0; c < CHSZ; c++) {
        float av = f[c*NN+a], bv = f[c*NN+bb];
        float dh, dl; two_sum(av, -bv, dh, dl);
        float p  = __fmul_rn(dh, dh);
        float pe = __fmaf_rn(dh, dh, -p);
        pe = __fmaf_rn(__fmul_rn(2.0f, dh), dl, pe);
        float t, er; two_sum(sh, p, t, er);
        sl = __fadd_rn(sl, __fadd_rn(er, pe));
        sh = t;
    }
    g_part[(b*NCHUNK + ch)*NE + e] = (double)sh + (double)sl;
}

// fixed-order deterministic reduction of the 32 chunk partials
__global__ void k_ew_red() {
    int idx = blockIdx.x*blockDim.x + threadIdx.x;
    if (idx >= BN*NE) return;
    int b = idx / NE, e = idx - b*NE;
    double acc = 0.0;
    #pragma unroll 8
    for (int ch = 0; ch < NCHUNK; ch++) acc += g_part[(b*NCHUNK + ch)*NE + e];
    int s = b*2 + 1;
    g_ws[s*NE + e] = acc;
    g_key[s*NE + e] = pack_key(acc, e);
}

// Parallel Boruvka, one block per tree; single fused min/argmin pass per round.
__global__ void __launch_bounds__(1024) k_boruvka() {
    extern __shared__ unsigned long long sh_u[];
    unsigned long long* minw = sh_u;       // NN
    int* parent = (int*)(minw + NN);       // NN
    int* hook   = parent + NN;             // NN
    __shared__ int total, flag;
    int s = blockIdx.x;
    const unsigned long long* key = g_key + s*NE;
    int* adj = g_adj + s*NN*4;
    int* deg = g_deg + s*NN;
    for (int i = threadIdx.x; i < NN; i += blockDim.x) { parent[i] = i; deg[i] = 0; }
    for (int i = threadIdx.x; i < NN*4; i += blockDim.x) adj[i] = -1;
    if (threadIdx.x == 0) total = 0;
    __syncthreads();
    for (int round = 0; round < 24; round++) {
        for (int i = threadIdx.x; i < NN; i += blockDim.x) {
            minw[i] = 0xFFFFFFFFFFFFFFFFull; hook[i] = -1;
        }
        __syncthreads();
        // fused min+argmin via packed key
        for (int e = threadIdx.x; e < NE; e += blockDim.x) {
            int a, b; edge_nodes(e, a, b);
            int ra = parent[a], rb = parent[b];
            if (ra != rb) {
                unsigned long long k = key[e];
                atomicMin(&minw[ra], k);
                atomicMin(&minw[rb], k);
            }
        }
        __syncthreads();
        // hook decision
        for (int i = threadIdx.x; i < NN; i += blockDim.x) {
            unsigned long long mk = minw[i];
            if (parent[i] == i && mk != 0xFFFFFFFFFFFFFFFFull) {
                int e = (int)(mk & 32767ull);
                int a, b; edge_nodes(e, a, b);
                int ra = parent[a], rb = parent[b];
                int other = (ra == i) ? rb : ra;
                bool mutual = (minw[other] == mk);
                if (!mutual || i < other) {
                    int da = atomicAdd(&deg[a], 1); adj[a*4+da] = b;
                    int db = atomicAdd(&deg[b], 1); adj[b*4+db] = a;
                    atomicAdd(&total, 1);
                    hook[i] = other;
                }
            }
        }
        __syncthreads();
        for (int i = threadIdx.x; i < NN; i += blockDim.x) {
            int t = hook[i];
            if (t >= 0) parent[i] = t;
        }
        __syncthreads();
        // flatten to star
        for (;;) {
            if (threadIdx.x == 0) flag = 0;
            __syncthreads();
            for (int i = threadIdx.x; i < NN; i += blockDim.x) {
                int p = parent[i], gp = parent[p];
                if (p != gp) { parent[i] = gp; flag = 1; }
            }
            __syncthreads();
            int f = flag;
            __syncthreads();
            if (!f) break;
        }
        if (total >= NN-1) break;
    }
}

// Level-synchronous BFS from node 0, state in shared memory.
__global__ void __launch_bounds__(512) k_bfs() {
    extern __shared__ int sh[];
    int* adj_s = sh;           // NN*4
    int* ord   = adj_s + NN*4; // NN
    int* par   = ord + NN;     // NN
    __shared__ int cnt;
    int s = blockIdx.x;
    const int* adj = g_adj + s*NN*4;
    int* loff = g_loff + s*(NN+4);
    for (int i = threadIdx.x; i < NN*4; i += blockDim.x) adj_s[i] = adj[i];
    if (threadIdx.x == 0) { ord[0] = 0; par[0] = 0; loff[0] = 0; loff[1] = 1; }
    __syncthreads();
    int cur = 0, curEnd = 1, lvl = 0;
    for (;;) {
        if (threadIdx.x == 0) cnt = 0;
        __syncthreads();
        for (int q = cur + threadIdx.x; q < curEnd; q += blockDim.x) {
            int u = ord[q], pu = par[u];
            #pragma unroll
            for (int j = 0; j < 4; j++) {
                int v = adj_s[u*4 + j];
                if (v >= 0 && v != pu) {
                    int pos = atomicAdd(&cnt, 1);
                    ord[curEnd + pos] = v;
                    par[v] = u;
                }
            }
        }
        __syncthreads();
        int c = cnt;
        __syncthreads();
        if (c == 0) break;
        lvl++;
        if (threadIdx.x == 0) loff[lvl+1] = curEnd + c;
        cur = curEnd; curEnd += c;
    }
    if (threadIdx.x == 0) g_nlev[s] = lvl + 1;
    for (int i = threadIdx.x; i < NN; i += blockDim.x) {
        g_ord[s*NN + i] = ord[i];
        g_par[s*NN + i] = par[i];
    }
}

// Parent-edge weights from precomputed edge distances.
__global__ void k_w() {
    int idx = blockIdx.x*blockDim.x + threadIdx.x;
    if (idx >= NTREE*NN) return;
    int s = idx / NN, i = idx - s*NN;
    if (i == 0) { g_w[idx] = 0.0f; return; }
    int p = g_par[s*NN + i];
    int e;
    if      (p == i-1)  { int r = i/WW, c = i%WW; e = r*(WW-1) + (c-1); }
    else if (p == i+1)  { int r = i/WW, c = i%WW; e = r*(WW-1) + c; }
    else if (p == i-WW) { e = NEH + (i-WW); }
    else                { e = NEH + i; }
    float sig = (s & 1) ? 1.0f : 0.02f;
    g_w[idx] = expf(-(float)g_ws[s*NE + e] / sig);
}

// Two-pass tree DP. One block per (batch, channel); small levels run on warp 0
// with __syncwarp to avoid full-block barriers on the deep-tree critical path.
__global__ void __launch_bounds__(256) k_filter(int t, int srcsel, int dst) {
    extern __shared__ float shf[];
    float* A = shf;              // NN
    float* S = A + NN;           // NN
    float* w = S + NN;           // NN
    int* par   = (int*)(w + NN); // NN
    int* ord   = par + NN;       // NN
    int* loffs = ord + NN;       // NN+4
    int b = blockIdx.x, c = blockIdx.y;
    int s = b*2 + t;
    int nl = g_nlev[s];
    const float* s1c = g_S + (b*(CCH+1) + c)*NN;
    const float* s1n = g_S + (b*(CCH+1) + CCH)*NN;
    for (int i = threadIdx.x; i < NN; i += blockDim.x) {
        float v;
        if (c == CCH)           v = 1.0f;
        else if (srcsel == 0)   v = g_prob[(b*CCH + c)*NN + i];
        else                    v = s1c[i] / s1n[i];
        A[i]   = v;
        w[i]   = g_w[s*NN + i];
        par[i] = g_par[s*NN + i];
        ord[i] = g_ord[s*NN + i];
    }
    for (int i = threadIdx.x; i <= nl; i += blockDim.x) loffs[i] = g_loff[s*(NN+4) + i];
    __syncthreads();
    int tid = threadIdx.x;
    // up: leaves -> root
    for (int d = nl - 1; d >= 1; d--) {
        int s0 = loffs[d], cnt2 = loffs[d+1] - s0;
        if (cnt2 <= 32) {
            if (tid < 32) {
                if (tid < cnt2) {
                    int v = ord[s0 + tid];
                    atomicAdd(&A[par[v]], w[v]*A[v]);
                }
                __syncwarp();
            }
        } else {
            __syncthreads();
            for (int k = tid; k < cnt2; k += blockDim.x) {
                int v = ord[s0 + k];
                atomicAdd(&A[par[v]], w[v]*A[v]);
            }
            __syncthreads();
        }
    }
    __syncthreads();
    if (tid == 0) S[0] = A[0];
    __syncthreads();
    // down: root -> leaves
    for (int d = 1; d < nl; d++) {
        int s0 = loffs[d], cnt2 = loffs[d+1] - s0;
        if (cnt2 <= 32) {
            if (tid < 32) {
                if (tid < cnt2) {
                    int v = ord[s0 + tid];
                    float wv = w[v], av = A[v];
                    S[v] = av + wv*(S[par[v]] - wv*av);
                }
                __syncwarp();
            }
        } else {
            __syncthreads();
            for (int k = tid; k < cnt2; k += blockDim.x) {
                int v = ord[s0 + k];
                float wv = w[v], av = A[v];
                S[v] = av + wv*(S[par[v]] - wv*av);
            }
            __syncthreads();
        }
    }
    __syncthreads();
    float* outS = ((dst == 0) ? g_S : g_S2) + (b*(CCH+1) + c)*NN;
    for (int i = threadIdx.x; i < NN; i += blockDim.x) outS[i] = S[i];
}

__global__ void k_loss(const float* __restrict__ roi) {
    __shared__ double sl[256], sn[256];
    int idx = blockIdx.x*blockDim.x + threadIdx.x;
    double l = 0.0, n = 0.0;
    if (idx < BN*NN) {
        int b = idx / NN, i = idx - b*NN;
        int h = i / WW, w = i - h*WW;
        float r = roi[b*(2*HH)*(2*WW) + (2*h)*(2*WW) + 2*w];
        n = (double)r;
        if (r != 0.0f) {
            float nrm = g_S2[(b*(CCH+1) + CCH)*NN + i];
            double acc = 0.0;
            for (int c = 0; c < CCH; c++) {
                float as = g_S2[(b*(CCH+1) + c)*NN + i] / nrm;
                acc += (double)fabsf(g_prob[(b*CCH + c)*NN + i] - as);
            }
            l = acc * (double)r;
        }
    }
    sl[threadIdx.x] = l; sn[threadIdx.x] = n;
    __syncthreads();
    for (int o = 128; o; o >>= 1) {
        if (threadIdx.x < o) { sl[threadIdx.x] += sl[threadIdx.x+o]; sn[threadIdx.x] += sn[threadIdx.x+o]; }
        __syncthreads();
    }
    if (threadIdx.x == 0) { atomicAdd(&g_acc[0], sl[0]); atomicAdd(&g_acc[1], sn[0]); }
}

__global__ void k_fin(float* out) {
    if (threadIdx.x == 0)
        out[0] = (g_acc[1] > 0.0) ? (float)(g_acc[0]/g_acc[1]) : 0.0f;
}

// ---------------- launch ----------------
extern "C" void kernel_launch(void* const* d_in, const int* in_sizes, int n_in,
                              void* d_out, int out_size) {
    const float* preds = (const float*)d_in[0];
    const float* lf    = (const float*)d_in[1];
    const float* hf    = (const float*)d_in[2];
    const float* roi   = (const float*)d_in[3];
    float* out = (float*)d_out;

    const int smem_boruvka = NN*8 + 2*NN*4;          // 147456
    const int smem_bfs     = 6*NN*4;                 // 221184
    const int smem_filter  = 5*NN*4 + (NN+4)*4;      // 221200
    cudaFuncSetAttribute(k_boruvka, cudaFuncAttributeMaxDynamicSharedMemorySize, smem_boruvka);
    cudaFuncSetAttribute(k_bfs,     cudaFuncAttributeMaxDynamicSharedMemorySize, smem_bfs);
    cudaFuncSetAttribute(k_filter,  cudaFuncAttributeMaxDynamicSharedMemorySize, smem_filter);

    k_zero   <<<1, 32>>>();
    k_sigmoid<<<(BN*CCH*NN + 255)/256, 256>>>(preds);
    k_ew_low <<<(BN*NE + 255)/256, 256>>>(lf);
    k_ew_high<<<(BN*NCHUNK*NE + 255)/256, 256>>>(hf);
    k_ew_red <<<(BN*NE + 255)/256, 256>>>();
    k_boruvka<<<NTREE, 1024, smem_boruvka>>>();
    k_bfs    <<<NTREE, 512, smem_bfs>>>();
    k_w      <<<(NTREE*NN + 255)/256, 256>>>();
    {
        dim3 g1(BN, CCH+1);
        k_filter<<<g1, 256, smem_filter>>>(0, 0, 0);
        k_filter<<<g1, 256, smem_filter>>>(1, 1, 1);
    }
    k_loss   <<<(BN*NN + 255)/256, 256>>>(roi);
    k_fin    <<<1, 32>>>(out);
}

// round 5
// speedup vs baseline: 13.4300x; 1.1973x over previous
#include <cuda_runtime.h>
#include <math.h>

#define BN 4
#define CCH 21
#define HH 96
#define WW 96
#define NN (HH*WW)          // 9216
#define NEH (HH*(WW-1))     // 9120
#define NEV ((HH-1)*WW)     // 9120
#define NE  (NEH+NEV)       // 18240
#define NTREE 8             // s = b*2 + t, t=0 low, t=1 high
#define NCHUNK 32
#define CHSZ  16            // 512 / NCHUNK

// ---------------- scratch ----------------
__device__ double g_ws[NTREE*NE];                 // edge squared distances (f64)
__device__ unsigned long long g_key[NTREE*NE];    // packed key: (f64bits & ~0x7FFF) | e
__device__ double g_part[BN*NCHUNK*NE];           // df64 partials
__device__ int    g_adj[NTREE*NN*4];
__device__ int    g_ord[NTREE*NN];                // node at BFS position
__device__ int    g_pp[NTREE*NN];                 // parent BFS position
__device__ int    g_loff[NTREE*(NN+4)];
__device__ int    g_nlev[NTREE];
__device__ float  g_w[NTREE*NN];                  // edge weight, BFS-position-indexed
__device__ float  g_prob[BN*CCH*NN];
__device__ float  g_S[BN*(CCH+1)*NN];
__device__ float  g_S2[BN*(CCH+1)*NN];
__device__ double g_acc[2];

__device__ __forceinline__ void edge_nodes(int e, int &a, int &b) {
    if (e < NEH) { int r = e / (WW-1); int c = e - r*(WW-1); a = r*WW + c; b = a + 1; }
    else         { a = e - NEH; b = a + WW; }
}

__device__ __forceinline__ unsigned long long pack_key(double w, int e) {
    unsigned long long kb = (unsigned long long)__double_as_longlong(w);
    return (kb & ~32767ull) | (unsigned long long)e;
}

__device__ __forceinline__ void two_sum(float a, float b, float &s, float &e) {
    s = __fadd_rn(a, b);
    float bp = __fsub_rn(s, a);
    e = __fadd_rn(__fsub_rn(a, __fsub_rn(s, bp)), __fsub_rn(b, bp));
}

// ---------------- kernels ----------------
__global__ void k_zero() {
    int i = blockIdx.x*blockDim.x + threadIdx.x;
    if (i < 2) g_acc[i] = 0.0;
}

__global__ void k_sigmoid(const float* __restrict__ preds) {
    int i = blockIdx.x*blockDim.x + threadIdx.x;
    if (i < BN*CCH*NN) g_prob[i] = 1.0f/(1.0f + expf(-preds[i]));
}

__global__ void k_ew_low(const float* __restrict__ lf) {
    int idx = blockIdx.x*blockDim.x + threadIdx.x;
    if (idx >= BN*NE) return;
    int b = idx / NE, e = idx - b*NE;
    int a, bb; edge_nodes(e, a, bb);
    const float* f = lf + b*3*NN;
    double acc = 0.0;
    #pragma unroll
    for (int c = 0; c < 3; c++) {
        double d = (double)f[c*NN+a] - (double)f[c*NN+bb];
        acc += d*d;
    }
    int s = b*2;
    g_ws[s*NE + e] = acc;
    g_key[s*NE + e] = pack_key(acc, e);
}

// df64 (float-float) squared distance on the fp32 pipe; per-chunk partials.
__global__ void k_ew_high(const float* __restrict__ hf) {
    int idx = blockIdx.x*blockDim.x + threadIdx.x;
    if (idx >= BN*NCHUNK*NE) return;
    int b = idx / (NCHUNK*NE);
    int r = idx - b*(NCHUNK*NE);
    int ch = r / NE, e = r - ch*NE;
    int a, bb; edge_nodes(e, a, bb);
    const float* f = hf + b*512*NN + ch*CHSZ*NN;
    float sh = 0.0f, sl = 0.0f;
    #pragma unroll
    for (int c = 0; c < CHSZ; c++) {
        float av = f[c*NN+a], bv = f[c*NN+bb];
        float dh, dl; two_sum(av, -bv, dh, dl);
        float p  = __fmul_rn(dh, dh);
        float pe = __fmaf_rn(dh, dh, -p);
        pe = __fmaf_rn(__fmul_rn(2.0f, dh), dl, pe);
        float t, er; two_sum(sh, p, t, er);
        sl = __fadd_rn(sl, __fadd_rn(er, pe));
        sh = t;
    }
    g_part[(b*NCHUNK + ch)*NE + e] = (double)sh + (double)sl;
}

__global__ void k_ew_red() {
    int idx = blockIdx.x*blockDim.x + threadIdx.x;
    if (idx >= BN*NE) return;
    int b = idx / NE, e = idx - b*NE;
    double acc = 0.0;
    #pragma unroll 8
    for (int ch = 0; ch < NCHUNK; ch++) acc += g_part[(b*NCHUNK + ch)*NE + e];
    int s = b*2 + 1;
    g_ws[s*NE + e] = acc;
    g_key[s*NE + e] = pack_key(acc, e);
}

// Parallel Boruvka, one block per tree; fused min/argmin via packed key;
// test-before-atomic; deg in smem.
__global__ void __launch_bounds__(1024) k_boruvka() {
    extern __shared__ unsigned long long sh_u[];
    unsigned long long* minw = sh_u;       // NN
    int* parent = (int*)(minw + NN);       // NN
    int* hook   = parent + NN;             // NN
    int* deg    = hook + NN;               // NN
    __shared__ int total, flag;
    int s = blockIdx.x;
    const unsigned long long* key = g_key + s*NE;
    int* adj = g_adj + s*NN*4;
    for (int i = threadIdx.x; i < NN; i += blockDim.x) { parent[i] = i; deg[i] = 0; }
    for (int i = threadIdx.x; i < NN*4; i += blockDim.x) adj[i] = -1;
    if (threadIdx.x == 0) total = 0;
    __syncthreads();
    for (int round = 0; round < 24; round++) {
        for (int i = threadIdx.x; i < NN; i += blockDim.x) {
            minw[i] = 0xFFFFFFFFFFFFFFFFull; hook[i] = -1;
        }
        __syncthreads();
        for (int e = threadIdx.x; e < NE; e += blockDim.x) {
            int a, b; edge_nodes(e, a, b);
            int ra = parent[a], rb = parent[b];
            if (ra != rb) {
                unsigned long long k = key[e];
                if (k < minw[ra]) atomicMin(&minw[ra], k);
                if (k < minw[rb]) atomicMin(&minw[rb], k);
            }
        }
        __syncthreads();
        for (int i = threadIdx.x; i < NN; i += blockDim.x) {
            unsigned long long mk = minw[i];
            if (parent[i] == i && mk != 0xFFFFFFFFFFFFFFFFull) {
                int e = (int)(mk & 32767ull);
                int a, b; edge_nodes(e, a, b);
                int ra = parent[a], rb = parent[b];
                int other = (ra == i) ? rb : ra;
                bool mutual = (minw[other] == mk);
                if (!mutual || i < other) {
                    int da = atomicAdd(&deg[a], 1); adj[a*4+da] = b;
                    int db = atomicAdd(&deg[b], 1); adj[b*4+db] = a;
                    atomicAdd(&total, 1);
                    hook[i] = other;
                }
            }
        }
        __syncthreads();
        for (int i = threadIdx.x; i < NN; i += blockDim.x) {
            int t = hook[i];
            if (t >= 0) parent[i] = t;
        }
        __syncthreads();
        for (;;) {
            if (threadIdx.x == 0) flag = 0;
            __syncthreads();
            for (int i = threadIdx.x; i < NN; i += blockDim.x) {
                int p = parent[i], gp = parent[p];
                if (p != gp) { parent[i] = gp; flag = 1; }
            }
            __syncthreads();
            int f = flag;
            __syncthreads();
            if (!f) break;
        }
        if (total >= NN-1) break;
    }
}

// Single-warp BFS (frontiers average <10 nodes -> no block barriers on the
// critical path). Emits BFS order, parent POSITIONS, level offsets.
__global__ void __launch_bounds__(256) k_bfs() {
    extern __shared__ int sh[];
    int* adj_s = sh;            // NN*4
    int* ord   = adj_s + NN*4;  // NN
    int* pp    = ord + NN;      // NN
    int* cnts  = pp + NN;       // 64 rotating level counters
    int s = blockIdx.x;
    const int* adj = g_adj + s*NN*4;
    int* loff = g_loff + s*(NN+4);
    for (int i = threadIdx.x; i < NN*4; i += blockDim.x) adj_s[i] = adj[i];
    for (int i = threadIdx.x; i < 64; i += blockDim.x) cnts[i] = 0;
    if (threadIdx.x == 0) { ord[0] = 0; pp[0] = 0; loff[0] = 0; loff[1] = 1; }
    __syncthreads();
    if (threadIdx.x < 32) {
        int lane = threadIdx.x;
        int cur = 0, curEnd = 1, lvl = 0;
        for (;;) {
            int slot = lvl & 63;
            for (int q = cur + lane; q < curEnd; q += 32) {
                int u = ord[q];
                int pu = ord[pp[q]];
                #pragma unroll
                for (int j = 0; j < 4; j++) {
                    int v = adj_s[u*4 + j];
                    if (v >= 0 && v != pu) {
                        int pos = atomicAdd(&cnts[slot], 1);
                        ord[curEnd + pos] = v;
                        pp[curEnd + pos] = q;
                    }
                }
            }
            __syncwarp();
            int c = cnts[slot];
            __syncwarp();
            if (lane == 0) cnts[slot] = 0;   // reused 64 levels later; safe
            if (c == 0) break;
            lvl++;
            if (lane == 0) loff[lvl+1] = curEnd + c;
            cur = curEnd; curEnd += c;
        }
        if (lane == 0) g_nlev[s] = lvl + 1;
    }
    __syncthreads();
    for (int i = threadIdx.x; i < NN; i += blockDim.x) {
        g_ord[s*NN + i] = ord[i];
        g_pp[s*NN + i]  = pp[i];
    }
}

// Edge weight per BFS position (MST edges are grid edges -> reuse g_ws).
__global__ void k_w() {
    int idx = blockIdx.x*blockDim.x + threadIdx.x;
    if (idx >= NTREE*NN) return;
    int s = idx / NN, k = idx - s*NN;
    if (k == 0) { g_w[idx] = 0.0f; return; }
    int v = g_ord[s*NN + k];
    int u = g_ord[s*NN + g_pp[s*NN + k]];
    int e;
    if      (u == v-1)  { int r = v/WW, c = v%WW; e = r*(WW-1) + (c-1); }
    else if (u == v+1)  { int r = v/WW, c = v%WW; e = r*(WW-1) + c; }
    else if (u == v-WW) { e = NEH + (v-WW); }
    else                { e = NEH + v; }
    float sig = (s & 1) ? 1.0f : 0.02f;
    g_w[idx] = expf(-(float)g_ws[s*NE + e] / sig);
}

// Two-pass tree DP in BFS-position space: levels are contiguous ranges,
// parent access via pp[] only. One block per (batch, channel).
__global__ void __launch_bounds__(256) k_filter(int t, int srcsel, int dst) {
    extern __shared__ float shf[];
    float* A = shf;               // NN  (position-indexed)
    float* S = A + NN;            // NN
    float* w = S + NN;            // NN
    int* pp    = (int*)(w + NN);  // NN
    int* ord   = pp + NN;         // NN
    int* loffs = ord + NN;        // NN+4
    int b = blockIdx.x, c = blockIdx.y;
    int s = b*2 + t;
    int nl = g_nlev[s];
    const float* s1c = g_S + (b*(CCH+1) + c)*NN;
    const float* s1n = g_S + (b*(CCH+1) + CCH)*NN;
    for (int i = threadIdx.x; i < NN; i += blockDim.x) {
        int node = g_ord[s*NN + i];
        float v;
        if (c == CCH)           v = 1.0f;
        else if (srcsel == 0)   v = g_prob[(b*CCH + c)*NN + node];
        else                    v = s1c[node] / s1n[node];
        A[i]   = v;
        w[i]   = g_w[s*NN + i];
        pp[i]  = g_pp[s*NN + i];
        ord[i] = node;
    }
    for (int i = threadIdx.x; i <= nl; i += blockDim.x) loffs[i] = g_loff[s*(NN+4) + i];
    __syncthreads();
    int tid = threadIdx.x;
    // up: leaves -> root
    for (int d = nl - 1; d >= 1; d--) {
        int s0 = loffs[d], cnt2 = loffs[d+1] - s0;
        if (cnt2 <= 32) {
            if (tid < 32) {
                if (tid < cnt2) {
                    int k = s0 + tid;
                    atomicAdd(&A[pp[k]], w[k]*A[k]);
                }
                __syncwarp();
            }
        } else {
            __syncthreads();
            for (int k = s0 + tid; k < s0 + cnt2; k += blockDim.x)
                atomicAdd(&A[pp[k]], w[k]*A[k]);
            __syncthreads();
        }
    }
    __syncthreads();
    if (tid == 0) S[0] = A[0];
    __syncthreads();
    // down: root -> leaves
    for (int d = 1; d < nl; d++) {
        int s0 = loffs[d], cnt2 = loffs[d+1] - s0;
        if (cnt2 <= 32) {
            if (tid < 32) {
                if (tid < cnt2) {
                    int k = s0 + tid;
                    float wv = w[k], av = A[k];
                    S[k] = av + wv*(S[pp[k]] - wv*av);
                }
                __syncwarp();
            }
        } else {
            __syncthreads();
            for (int k = s0 + tid; k < s0 + cnt2; k += blockDim.x) {
                float wv = w[k], av = A[k];
                S[k] = av + wv*(S[pp[k]] - wv*av);
            }
            __syncthreads();
        }
    }
    __syncthreads();
    float* outS = ((dst == 0) ? g_S : g_S2) + (b*(CCH+1) + c)*NN;
    for (int i = threadIdx.x; i < NN; i += blockDim.x) outS[ord[i]] = S[i];
}

__global__ void k_loss(const float* __restrict__ roi) {
    __shared__ double sl[256], sn[256];
    int idx = blockIdx.x*blockDim.x + threadIdx.x;
    double l = 0.0, n = 0.0;
    if (idx < BN*NN) {
        int b = idx / NN, i = idx - b*NN;
        int h = i / WW, w = i - h*WW;
        float r = roi[b*(2*HH)*(2*WW) + (2*h)*(2*WW) + 2*w];
        n = (double)r;
        if (r != 0.0f) {
            float nrm = g_S2[(b*(CCH+1) + CCH)*NN + i];
            double acc = 0.0;
            for (int c = 0; c < CCH; c++) {
                float as = g_S2[(b*(CCH+1) + c)*NN + i] / nrm;
                acc += (double)fabsf(g_prob[(b*CCH + c)*NN + i] - as);
            }
            l = acc * (double)r;
        }
    }
    sl[threadIdx.x] = l; sn[threadIdx.x] = n;
    __syncthreads();
    for (int o = 128; o; o >>= 1) {
        if (threadIdx.x < o) { sl[threadIdx.x] += sl[threadIdx.x+o]; sn[threadIdx.x] += sn[threadIdx.x+o]; }
        __syncthreads();
    }
    if (threadIdx.x == 0) { atomicAdd(&g_acc[0], sl[0]); atomicAdd(&g_acc[1], sn[0]); }
}

__global__ void k_fin(float* out) {
    if (threadIdx.x == 0)
        out[0] = (g_acc[1] > 0.0) ? (float)(g_acc[0]/g_acc[1]) : 0.0f;
}

// ---------------- launch ----------------
extern "C" void kernel_launch(void* const* d_in, const int* in_sizes, int n_in,
                              void* d_out, int out_size) {
    const float* preds = (const float*)d_in[0];
    const float* lf    = (const float*)d_in[1];
    const float* hf    = (const float*)d_in[2];
    const float* roi   = (const float*)d_in[3];
    float* out = (float*)d_out;

    const int smem_boruvka = NN*8 + 3*NN*4;          // 184320
    const int smem_bfs     = NN*4*4 + 2*NN*4 + 256;  // 221440
    const int smem_filter  = 5*NN*4 + (NN+4)*4;      // 221200
    cudaFuncSetAttribute(k_boruvka, cudaFuncAttributeMaxDynamicSharedMemorySize, smem_boruvka);
    cudaFuncSetAttribute(k_bfs,     cudaFuncAttributeMaxDynamicSharedMemorySize, smem_bfs);
    cudaFuncSetAttribute(k_filter,  cudaFuncAttributeMaxDynamicSharedMemorySize, smem_filter);

    k_zero   <<<1, 32>>>();
    k_sigmoid<<<(BN*CCH*NN + 255)/256, 256>>>(preds);
    k_ew_low <<<(BN*NE + 255)/256, 256>>>(lf);
    k_ew_high<<<(BN*NCHUNK*NE + 255)/256, 256>>>(hf);
    k_ew_red <<<(BN*NE + 255)/256, 256>>>();
    k_boruvka<<<NTREE, 1024, smem_boruvka>>>();
    k_bfs    <<<NTREE, 256, smem_bfs>>>();
    k_w      <<<(NTREE*NN + 255)/256, 256>>>();
    {
        dim3 g1(BN, CCH+1);
        k_filter<<<g1, 256, smem_filter>>>(0, 0, 0);
        k_filter<<<g1, 256, smem_filter>>>(1, 1, 1);
    }
    k_loss   <<<(BN*NN + 255)/256, 256>>>(roi);
    k_fin    <<<1, 32>>>(out);
}